// round 6
// baseline (speedup 1.0000x reference)
#include <cuda_runtime.h>

#define BB 512
#define QL 128
#define AL 512
#define EE 300
#define FF 400
#define VMAX 50000
#define NEG_INF (-1e30f)

// ---------------- scratch (device globals; no allocations allowed) ----------
__device__ float g_Wt[900 * 400];                    // W transposed: [(e*3+k)][f]
__device__ float g_Q[(size_t)BB * FF * QL];          // 104.8 MB
__device__ float g_A[(size_t)BB * FF * AL];          // 419 MB
__device__ float g_P[(size_t)BB * FF * QL];          // 104.8 MB
__device__ float g_maxQ[BB * QL];
__device__ float g_maxA[BB * AL];

__device__ __forceinline__ void atomicMaxF(float* a, float v) {
    if (v >= 0.f) atomicMax((int*)a, __float_as_int(v));
    else          atomicMin((unsigned int*)a, __float_as_uint(v));
}

// ---------------- K0: transpose conv weights + init maxes -------------------
__global__ void init_kernel(const float* __restrict__ conv_w) {
    int i = blockIdx.x * 256 + threadIdx.x;
    if (i < 900 * 400) {
        int e3k = i / 400, f = i - e3k * 400;
        g_Wt[i] = conv_w[f * 900 + e3k];             // g_Wt[e3k*400 + f]
    }
    if (i < BB * QL) g_maxQ[i] = NEG_INF;
    if (i < BB * AL) g_maxA[i] = NEG_INF;
}

// ---------------- K1: embedding gather + conv1d (k=3, pad=1) ----------------
// grid: (ftile=5, seg=5, b=512); block 256.
// seg 0: question (L=128, one 128-tile); seg 1..4: answer 128-tiles.
// Per thread: 5 f x 8 l register tile -> 40 FFMA per (e,k) step, 13 LDS.
// NOTE: indices are int32 (JAX x64-disabled demotes the declared int64).
__global__ __launch_bounds__(256) void conv_kernel(
    const int* __restrict__ qidx, const int* __restrict__ aidx,
    const float* __restrict__ emb, const float* __restrict__ bias)
{
    const int tid = threadIdx.x;
    const int tl = tid & 15, tf = tid >> 4;
    const int f0 = blockIdx.x * 80;
    const int seg = blockIdx.y;
    const int b = blockIdx.z;
    const bool isQ = (seg == 0);
    const int L = isQ ? QL : AL;
    const int l0 = isQ ? 0 : (seg - 1) * 128;
    const int* ip = isQ ? (qidx + (size_t)b * QL) : (aidx + (size_t)b * AL);
    float* outp = isQ ? (g_Q + (size_t)b * FF * QL) : (g_A + (size_t)b * FF * AL);

    __shared__ float Xs[10 * 130];   // [e_local][row]  (rows: l0-1 .. l0+128)
    __shared__ float Ws[30 * 80];    // [(e_local*3+k)][f_local]
    __shared__ int   idx_s[130];

    for (int r = tid; r < 130; r += 256) {
        int gl = l0 - 1 + r;
        int id = -1;
        if (gl >= 0 && gl < L) {
            id = ip[gl];
            if (id < 0) id = 0;
            if (id > VMAX) id = VMAX;      // defensive clamp (dtype hedge)
        }
        idx_s[r] = id;                     // -1 => zero pad
    }

    float acc[5][8];
    #pragma unroll
    for (int i = 0; i < 5; i++) {
        float bv = bias[f0 + tf + 16 * i];
        #pragma unroll
        for (int j = 0; j < 8; j++) acc[i][j] = bv;
    }

    for (int ec = 0; ec < 30; ec++) {        // E=300 in chunks of 10
        const int e0 = ec * 10;
        __syncthreads();
        for (int t = tid; t < 2400; t += 256) {
            int ff2 = t % 80, r = t / 80;    // r = e_local*3 + k
            Ws[t] = g_Wt[(e0 * 3 + r) * 400 + f0 + ff2];
        }
        for (int t = tid; t < 1300; t += 256) {
            int r = t / 10, el = t - r * 10;
            int id = idx_s[r];
            Xs[el * 130 + r] = (id >= 0) ? emb[(size_t)id * EE + e0 + el] : 0.f;
        }
        __syncthreads();
        #pragma unroll
        for (int el = 0; el < 10; el++) {
            #pragma unroll
            for (int k = 0; k < 3; k++) {
                float wr[5], xr[8];
                #pragma unroll
                for (int i = 0; i < 5; i++) wr[i] = Ws[(el * 3 + k) * 80 + tf + 16 * i];
                #pragma unroll
                for (int j = 0; j < 8; j++) xr[j] = Xs[el * 130 + tl + 16 * j + k];
                #pragma unroll
                for (int i = 0; i < 5; i++)
                    #pragma unroll
                    for (int j = 0; j < 8; j++)
                        acc[i][j] += wr[i] * xr[j];
            }
        }
    }

    #pragma unroll
    for (int i = 0; i < 5; i++) {
        const int f = f0 + tf + 16 * i;
        #pragma unroll
        for (int j = 0; j < 8; j++)
            outp[(size_t)f * L + l0 + tl + 16 * j] = acc[i][j];
    }
}

// ---------------- K2: P[b] = U^T @ Q[b]   ([400g x 128q], K=400f) -----------
// grid: (gtile=5, b=512); block 256; per-thread 5g x 8q.
__global__ __launch_bounds__(256) void pgemm_kernel(const float* __restrict__ Umat) {
    const int tid = threadIdx.x;
    const int tq = tid & 15, tg = tid >> 4;
    const int g0 = blockIdx.x * 80;
    const int b = blockIdx.y;
    __shared__ float Us[8 * 80];
    __shared__ float Qs[8 * 128];
    float acc[5][8];
    #pragma unroll
    for (int i = 0; i < 5; i++)
        #pragma unroll
        for (int j = 0; j < 8; j++) acc[i][j] = 0.f;

    const float* Qb = g_Q + (size_t)b * FF * QL;
    for (int fc = 0; fc < 50; fc++) {
        const int fbase = fc * 8;
        __syncthreads();
        for (int t = tid; t < 640; t += 256) {
            int gg = t % 80, ff2 = t / 80;
            Us[t] = Umat[(fbase + ff2) * 400 + g0 + gg];
        }
        for (int t = tid; t < 1024; t += 256) {
            int qq = t & 127, ff2 = t >> 7;
            Qs[t] = Qb[(size_t)(fbase + ff2) * QL + qq];
        }
        __syncthreads();
        #pragma unroll
        for (int ff2 = 0; ff2 < 8; ff2++) {
            float ur[5], qr[8];
            #pragma unroll
            for (int i = 0; i < 5; i++) ur[i] = Us[ff2 * 80 + tg + 16 * i];
            #pragma unroll
            for (int j = 0; j < 8; j++) qr[j] = Qs[ff2 * 128 + tq + 16 * j];
            #pragma unroll
            for (int i = 0; i < 5; i++)
                #pragma unroll
                for (int j = 0; j < 8; j++)
                    acc[i][j] += ur[i] * qr[j];
        }
    }
    float* Pb = g_P + (size_t)b * FF * QL;
    #pragma unroll
    for (int i = 0; i < 5; i++)
        #pragma unroll
        for (int j = 0; j < 8; j++)
            Pb[(size_t)(g0 + tg + 16 * i) * QL + tq + 16 * j] = acc[i][j];
}

// ---------------- K3: G = tanh(P^T A) tile + row/col maxes (G not stored) ---
// grid: (atile=4, b=512); block 256; per-thread 8q x 8a.
__global__ __launch_bounds__(256) void gmax_kernel() {
    const int tid = threadIdx.x;
    const int ta = tid & 15, tq = tid >> 4;
    const int a0 = blockIdx.x * 128;
    const int b = blockIdx.y;
    __shared__ float Ps[8 * 128], As[8 * 128];
    __shared__ float smq[128], sma[128];

    float acc[8][8];
    #pragma unroll
    for (int i = 0; i < 8; i++)
        #pragma unroll
        for (int j = 0; j < 8; j++) acc[i][j] = 0.f;

    const float* Pb = g_P + (size_t)b * FF * QL;
    const float* Ab = g_A + (size_t)b * FF * AL;
    for (int gc = 0; gc < 50; gc++) {
        const int gbase = gc * 8;
        __syncthreads();
        for (int t = tid; t < 1024; t += 256) {
            int col = t & 127, gg = t >> 7;
            Ps[t] = Pb[(size_t)(gbase + gg) * QL + col];
            As[t] = Ab[(size_t)(gbase + gg) * AL + a0 + col];
        }
        __syncthreads();
        #pragma unroll
        for (int gg = 0; gg < 8; gg++) {
            float pr[8], ar[8];
            #pragma unroll
            for (int i = 0; i < 8; i++) pr[i] = Ps[gg * 128 + tq + 16 * i];
            #pragma unroll
            for (int j = 0; j < 8; j++) ar[j] = As[gg * 128 + ta + 16 * j];
            #pragma unroll
            for (int i = 0; i < 8; i++)
                #pragma unroll
                for (int j = 0; j < 8; j++)
                    acc[i][j] += pr[i] * ar[j];
        }
    }

    if (tid < 128) { smq[tid] = NEG_INF; sma[tid] = NEG_INF; }
    __syncthreads();

    float mq[8], ma[8];
    #pragma unroll
    for (int i = 0; i < 8; i++) mq[i] = NEG_INF;
    #pragma unroll
    for (int j = 0; j < 8; j++) ma[j] = NEG_INF;
    #pragma unroll
    for (int i = 0; i < 8; i++)
        #pragma unroll
        for (int j = 0; j < 8; j++) {
            float gv = tanhf(acc[i][j]);
            mq[i] = fmaxf(mq[i], gv);
            ma[j] = fmaxf(ma[j], gv);
        }
    #pragma unroll
    for (int i = 0; i < 8; i++) atomicMaxF(&smq[tq + 16 * i], mq[i]);
    #pragma unroll
    for (int j = 0; j < 8; j++) atomicMaxF(&sma[ta + 16 * j], ma[j]);
    __syncthreads();
    if (tid < 128) {
        atomicMaxF(&g_maxQ[b * QL + tid], smq[tid]);         // 4 blocks contend
        atomicMaxF(&g_maxA[b * AL + a0 + tid], sma[tid]);    // exclusive range
    }
}

// ---------------- K4: softmax + pooled rQ/rA + cosine -----------------------
// grid: 512 blocks (one per b); block 256.
__global__ __launch_bounds__(256) void final_kernel(float* __restrict__ out) {
    const int tid = threadIdx.x;
    const int b = blockIdx.x;
    __shared__ float wq[128], wa[512], rq[400], ra[400], red[256];
    __shared__ float s_res[3];

    // --- softmax over maxQ (128) ---
    float v = (tid < 128) ? g_maxQ[b * QL + tid] : NEG_INF;
    red[tid] = v; __syncthreads();
    for (int s = 128; s > 0; s >>= 1) { if (tid < s) red[tid] = fmaxf(red[tid], red[tid + s]); __syncthreads(); }
    float m = red[0]; __syncthreads();
    float e = (tid < 128) ? __expf(v - m) : 0.f;
    red[tid] = e; __syncthreads();
    for (int s = 128; s > 0; s >>= 1) { if (tid < s) red[tid] += red[tid + s]; __syncthreads(); }
    float ssum = red[0]; __syncthreads();
    if (tid < 128) wq[tid] = e / ssum;

    // --- softmax over maxA (512) ---
    float va0 = g_maxA[b * AL + tid], va1 = g_maxA[b * AL + 256 + tid];
    red[tid] = fmaxf(va0, va1); __syncthreads();
    for (int s = 128; s > 0; s >>= 1) { if (tid < s) red[tid] = fmaxf(red[tid], red[tid + s]); __syncthreads(); }
    float mA = red[0]; __syncthreads();
    float ea0 = __expf(va0 - mA), ea1 = __expf(va1 - mA);
    red[tid] = ea0 + ea1; __syncthreads();
    for (int s = 128; s > 0; s >>= 1) { if (tid < s) red[tid] += red[tid + s]; __syncthreads(); }
    float sA = red[0]; __syncthreads();
    wa[tid] = ea0 / sA; wa[256 + tid] = ea1 / sA;
    __syncthreads();

    // --- rQ[f] = Q[b,f,:]·wq ;  rA[f] = A[b,f,:]·wa  (8 lanes per f) ---
    const int lane = tid & 31, wid = tid >> 5, sub = lane & 7, fl = lane >> 3;
    const float* Qb = g_Q + (size_t)b * FF * QL;
    const float* Ab = g_A + (size_t)b * FF * AL;
    for (int fb = wid * 4; fb < 400; fb += 32) {
        const int f = fb + fl;
        float accq = 0.f;
        for (int q = sub; q < QL; q += 8) accq += Qb[(size_t)f * QL + q] * wq[q];
        accq += __shfl_xor_sync(0xffffffffu, accq, 1);
        accq += __shfl_xor_sync(0xffffffffu, accq, 2);
        accq += __shfl_xor_sync(0xffffffffu, accq, 4);
        if (sub == 0) rq[f] = accq;
        float acca = 0.f;
        for (int a = sub; a < AL; a += 8) acca += Ab[(size_t)f * AL + a] * wa[a];
        acca += __shfl_xor_sync(0xffffffffu, acca, 1);
        acca += __shfl_xor_sync(0xffffffffu, acca, 2);
        acca += __shfl_xor_sync(0xffffffffu, acca, 4);
        if (sub == 0) ra[f] = acca;
    }
    __syncthreads();

    // --- cosine ---
    float dqa = 0.f, dqq = 0.f, daa = 0.f;
    for (int f = tid; f < 400; f += 256) {
        float x = rq[f], y = ra[f];
        dqa += x * y; dqq += x * x; daa += y * y;
    }
    red[tid] = dqa; __syncthreads();
    for (int s = 128; s > 0; s >>= 1) { if (tid < s) red[tid] += red[tid + s]; __syncthreads(); }
    if (tid == 0) s_res[0] = red[0];
    __syncthreads();
    red[tid] = dqq; __syncthreads();
    for (int s = 128; s > 0; s >>= 1) { if (tid < s) red[tid] += red[tid + s]; __syncthreads(); }
    if (tid == 0) s_res[1] = red[0];
    __syncthreads();
    red[tid] = daa; __syncthreads();
    for (int s = 128; s > 0; s >>= 1) { if (tid < s) red[tid] += red[tid + s]; __syncthreads(); }
    if (tid == 0) {
        s_res[2] = red[0];
        float nQ = fmaxf(sqrtf(s_res[1]), 1e-8f);
        float nA = fmaxf(sqrtf(s_res[2]), 1e-8f);
        out[b] = s_res[0] / (nQ * nA);
    }
}

// ---------------- launch -----------------------------------------------------
extern "C" void kernel_launch(void* const* d_in, const int* in_sizes, int n_in,
                              void* d_out, int out_size) {
    (void)in_sizes; (void)n_in; (void)out_size;
    const int*   question = (const int*)d_in[0];
    const int*   answer   = (const int*)d_in[1];
    const float* emb      = (const float*)d_in[2];
    const float* conv_w   = (const float*)d_in[3];
    const float* conv_b   = (const float*)d_in[4];
    const float* Umat     = (const float*)d_in[5];
    float* out = (float*)d_out;

    init_kernel<<<(900 * 400 + 255) / 256, 256>>>(conv_w);
    conv_kernel<<<dim3(5, 5, 512), 256>>>(question, answer, emb, conv_b);
    pgemm_kernel<<<dim3(5, 512), 256>>>(Umat);
    gmax_kernel<<<dim3(4, 512), 256>>>();
    final_kernel<<<512, 256>>>(out);
}